// round 1
// baseline (speedup 1.0000x reference)
#include <cuda_runtime.h>

// VectorQuantizer: z (16,64,64,64) fp32, codebook (1024,64) fp32
// out = [z_q_out flattened (b,c,h,w) : 1048576 floats][loss : 1 float]

#define B_    16
#define C_    64
#define H_    64
#define W_    64
#define HW_   (H_ * W_)        // 4096
#define N_    (B_ * HW_)       // 65536 vectors
#define NE_   1024             // codebook entries
#define D_    64               // embedding dim
#define TPB   128
#define NBLK  (N_ / TPB)       // 512 blocks
#define CHUNK 256              // codebook entries staged in smem per iteration

__device__ double g_partial[NBLK];
__device__ float  g_ee[NE_];

// Precompute ||e_k||^2 for all codebook entries (mirrors jnp.sum(cb*cb, axis=1))
__global__ void vq_ee_kernel(const float* __restrict__ cb) {
    int k = blockIdx.x * blockDim.x + threadIdx.x;
    if (k < NE_) {
        const float* e = cb + (size_t)k * D_;
        float s = 0.f;
#pragma unroll
        for (int c = 0; c < D_; c++) s = fmaf(e[c], e[c], s);
        g_ee[k] = s;
    }
}

// Main: one thread per vector. z vector lives in registers; codebook is
// streamed through shared memory in CHUNK-entry tiles (broadcast LDS.128 in
// the dot loop: all lanes read the same address -> conflict-free).
__global__ __launch_bounds__(TPB) void vq_main_kernel(
    const float* __restrict__ z, const float* __restrict__ cb,
    float* __restrict__ out, int write_zq)
{
    __shared__ float  s_e[CHUNK * D_];   // 64 KB
    __shared__ float  s_ee[CHUNK];
    __shared__ double s_red[TPB / 32];

    const int n  = blockIdx.x * TPB + threadIdx.x;
    const int b  = n / HW_;
    const int hw = n - b * HW_;
    const float* zbase = z + (size_t)b * (C_ * HW_) + hw;

    // Load the vector (coalesced across threads per channel: stride HW_)
    float zr[D_];
#pragma unroll
    for (int c = 0; c < D_; c++) zr[c] = zbase[(size_t)c * HW_];

    // ||z||^2 in fp32 (mirrors reference's fp32 accumulation scale)
    float zz = 0.f;
#pragma unroll
    for (int c = 0; c < D_; c++) zz = fmaf(zr[c], zr[c], zz);

    float best_d = 3.402823466e38f;
    int   best_i = 0;

    for (int k0 = 0; k0 < NE_; k0 += CHUNK) {
        __syncthreads();
        // Cooperative, coalesced chunk load: CHUNK*D_ floats = 4096 float4
        {
            const float4* src = (const float4*)(cb + (size_t)k0 * D_);
            float4* dst = (float4*)s_e;
            for (int i = threadIdx.x; i < CHUNK * D_ / 4; i += TPB) dst[i] = src[i];
            for (int i = threadIdx.x; i < CHUNK; i += TPB) s_ee[i] = g_ee[k0 + i];
        }
        __syncthreads();

#pragma unroll 1
        for (int k = 0; k < CHUNK; k++) {
            const float* ek = s_e + k * D_;
            float a0 = 0.f, a1 = 0.f, a2 = 0.f, a3 = 0.f;
#pragma unroll
            for (int c = 0; c < D_; c += 4) {
                float4 ev = *(const float4*)(ek + c);   // broadcast LDS.128
                a0 = fmaf(zr[c + 0], ev.x, a0);
                a1 = fmaf(zr[c + 1], ev.y, a1);
                a2 = fmaf(zr[c + 2], ev.z, a2);
                a3 = fmaf(zr[c + 3], ev.w, a3);
            }
            float dot = (a0 + a1) + (a2 + a3);
            // Mirror reference rounding: (zz + ee) then subtract 2*dot.
            // 2*dot is exact, so FMA vs separate sub round identically.
            float d = __fadd_rn(__fadd_rn(zz, s_ee[k]), -2.0f * dot);
            if (d < best_d) { best_d = d; best_i = k0 + k; }  // strict < == first-occurrence argmin
        }
    }

    // Epilogue: gather winning entry, emit z_q (b,c,h,w), accumulate loss in fp64
    const float* eb = cb + (size_t)best_i * D_;
    float* obase = out + (size_t)b * (C_ * HW_) + hw;
    double lsum = 0.0;
#pragma unroll
    for (int c = 0; c < D_; c++) {
        float e = eb[c];
        float diff = e - zr[c];
        lsum += (double)diff * (double)diff;
        if (write_zq) obase[(size_t)c * HW_] = e;   // coalesced per channel
    }

    // Deterministic block reduction (no atomics)
#pragma unroll
    for (int off = 16; off; off >>= 1)
        lsum += __shfl_down_sync(0xffffffffu, lsum, off);
    const int lane = threadIdx.x & 31;
    const int wid  = threadIdx.x >> 5;
    if (lane == 0) s_red[wid] = lsum;
    __syncthreads();
    if (threadIdx.x == 0) {
        double t = 0.0;
#pragma unroll
        for (int w = 0; w < TPB / 32; w++) t += s_red[w];
        g_partial[blockIdx.x] = t;
    }
}

// Deterministic final loss: loss = beta*m + m, m = mean((z_q - z)^2)
__global__ void vq_finalize_kernel(float* __restrict__ out, int loss_idx) {
    double s = 0.0;
    for (int i = 0; i < NBLK; i++) s += g_partial[i];
    float m = (float)(s / (double)((long long)N_ * D_));
    out[loss_idx] = 0.25f * m + m;
}

extern "C" void kernel_launch(void* const* d_in, const int* in_sizes, int n_in,
                              void* d_out, int out_size) {
    const float* z  = (const float*)d_in[0];
    const float* cb = (const float*)d_in[1];
    float* out = (float*)d_out;

    const int zq_elems = N_ * C_;               // 1048576
    const int write_zq = (out_size >= zq_elems) ? 1 : 0;

    vq_ee_kernel<<<NE_ / 128, 128>>>(cb);
    vq_main_kernel<<<NBLK, TPB>>>(z, cb, out, write_zq);

    if (out_size == 1) {
        vq_finalize_kernel<<<1, 1>>>(out, 0);           // loss-only output
    } else if (out_size > zq_elems) {
        vq_finalize_kernel<<<1, 1>>>(out, zq_elems);    // [z_q | loss]
    }
}

// round 2
// speedup vs baseline: 1.3333x; 1.3333x over previous
#include <cuda_runtime.h>

// VectorQuantizer: z (16,64,64,64) fp32, codebook (1024,64) fp32
// out = [z_q flattened (b,c,h,w) : 1048576 floats][loss : 1 float]
//
// Strategy: fp32 mandatory (a single argmin flip vs reference costs ~5e-3
// rel_err > 1e-3 tolerance). Distance loop uses packed fma.rn.f32x2 along the
// embedding dim (no operand duplication needed), halving FMA-pipe issue cost.
// zz / ee / d rounding structure kept bit-identical to the validated round-1
// kernel so the argmin never flips.

#define B_    16
#define C_    64
#define HW_   4096
#define N_    (B_ * HW_)       // 65536 vectors
#define NE_   1024
#define D_    64
#define TPB   128
#define NBLK  (N_ / TPB)       // 512 blocks
#define CHUNK 128              // codebook entries staged in smem per iter (32KB)

typedef unsigned long long ull;

__device__ double g_partial[NBLK];
__device__ float  g_ee[NE_];

#define FMA_F32X2(d, a, b, c) \
    asm("fma.rn.f32x2 %0, %1, %2, %3;" : "=l"(d) : "l"(a), "l"(b), "l"(c))
#define PACK_F32X2(out, lo, hi) \
    asm("mov.b64 %0, {%1, %2};" : "=l"(out) : "r"(lo), "r"(hi))
#define UNPACK_F32X2(lo, hi, in) \
    asm("mov.b64 {%0, %1}, %2;" : "=r"(lo), "=r"(hi) : "l"(in))

// ||e_k||^2, bitwise-identical accumulation order to round 1 (sequential fmaf
// over c ascending) — this order is load-bearing for argmin reproducibility.
__global__ void vq_ee_kernel(const float* __restrict__ cb) {
    int k = blockIdx.x * blockDim.x + threadIdx.x;
    if (k < NE_) {
        const float4* e = (const float4*)(cb + (size_t)k * D_);
        float s = 0.f;
#pragma unroll
        for (int c = 0; c < D_ / 4; c++) {
            float4 v = e[c];
            s = fmaf(v.x, v.x, s);
            s = fmaf(v.y, v.y, s);
            s = fmaf(v.z, v.z, s);
            s = fmaf(v.w, v.w, s);
        }
        g_ee[k] = s;
    }
}

__global__ __launch_bounds__(TPB) void vq_main_kernel(
    const float* __restrict__ z, const float* __restrict__ cb,
    float* __restrict__ out, int write_zq)
{
    __shared__ __align__(16) float s_e[CHUNK * D_];   // 32 KB
    __shared__ float  s_ee[CHUNK];
    __shared__ double s_red[TPB / 32];

    const int n  = blockIdx.x * TPB + threadIdx.x;
    const int b  = n / HW_;
    const int hw = n - b * HW_;
    const float* zbase = z + (size_t)b * (C_ * HW_) + hw;

    // Load z vector; compute zz with round-1's exact sequential fmaf order;
    // pack consecutive dims (2j, 2j+1) into f32x2 carriers.
    ull   z2[D_ / 2];
    float zs[D_];               // kept for epilogue (loss + optional ref reads)
    float zz = 0.f;
#pragma unroll
    for (int c = 0; c < D_; c++) {
        zs[c] = zbase[(size_t)c * HW_];
        zz = fmaf(zs[c], zs[c], zz);
    }
#pragma unroll
    for (int j = 0; j < D_ / 2; j++)
        PACK_F32X2(z2[j], __float_as_uint(zs[2 * j]), __float_as_uint(zs[2 * j + 1]));

    float best_d = 3.402823466e38f;
    int   best_i = 0;

    for (int k0 = 0; k0 < NE_; k0 += CHUNK) {
        __syncthreads();
        {   // cooperative coalesced chunk load: CHUNK*D_/4 = 2048 float4
            const float4* src = (const float4*)(cb + (size_t)k0 * D_);
            float4* dst = (float4*)s_e;
#pragma unroll
            for (int i = 0; i < CHUNK * D_ / 4 / TPB; i++)
                dst[threadIdx.x + i * TPB] = src[threadIdx.x + i * TPB];
            s_ee[threadIdx.x] = g_ee[k0 + threadIdx.x];   // CHUNK == TPB
        }
        __syncthreads();

#pragma unroll 4
        for (int k = 0; k < CHUNK; k++) {
            const ulonglong2* e2 = (const ulonglong2*)(s_e + k * D_);
            ull a0 = 0ull, a1 = 0ull;   // bitwise {0.f, 0.f}
#pragma unroll
            for (int j = 0; j < D_ / 4; j++) {
                ulonglong2 ev = e2[j];            // broadcast LDS.128: dims 4j..4j+3
                FMA_F32X2(a0, z2[2 * j],     ev.x, a0);   // lanes: dims =0,1 (mod 4)
                FMA_F32X2(a1, z2[2 * j + 1], ev.y, a1);   // lanes: dims =2,3 (mod 4)
            }
            unsigned r0, r1, r2, r3;
            UNPACK_F32X2(r0, r1, a0);
            UNPACK_F32X2(r2, r3, a1);
            // exact round-1 reduction order: (a0+a1)+(a2+a3) over dim-residues
            float dot = __fadd_rn(__fadd_rn(__uint_as_float(r0), __uint_as_float(r2)),
                                  __fadd_rn(__uint_as_float(r1), __uint_as_float(r3)));
            // NOTE: residue mapping — a0.lo=res0, a0.hi=res1, a1.lo=res2, a1.hi=res3
            // so (res0+res1)+(res2+res3) = (r0+r2' ...) — keep pairing (r0,r1),(r2,r3):
            dot = __fadd_rn(__fadd_rn(__uint_as_float(r0), __uint_as_float(r1)),
                            __fadd_rn(__uint_as_float(r2), __uint_as_float(r3)));
            float d = __fadd_rn(__fadd_rn(zz, s_ee[k]), -2.0f * dot);
            if (d < best_d) { best_d = d; best_i = k0 + k; }  // strict <: first occurrence
        }
    }

    // Epilogue: gather winning entry, emit z_q, accumulate loss in fp64
    const float* eb = cb + (size_t)best_i * D_;
    float* obase = out + (size_t)b * (C_ * HW_) + hw;
    double lsum = 0.0;
#pragma unroll
    for (int c = 0; c < D_; c++) {
        float e = eb[c];
        float diff = e - zs[c];
        lsum += (double)diff * (double)diff;
        if (write_zq) obase[(size_t)c * HW_] = e;
    }

#pragma unroll
    for (int off = 16; off; off >>= 1)
        lsum += __shfl_down_sync(0xffffffffu, lsum, off);
    const int lane = threadIdx.x & 31;
    const int wid  = threadIdx.x >> 5;
    if (lane == 0) s_red[wid] = lsum;
    __syncthreads();
    if (threadIdx.x == 0) {
        double t = 0.0;
#pragma unroll
        for (int w = 0; w < TPB / 32; w++) t += s_red[w];
        g_partial[blockIdx.x] = t;
    }
}

// Deterministic parallel finalize: fixed-shape tree over 512 partials.
__global__ void vq_finalize_kernel(float* __restrict__ out, int loss_idx) {
    __shared__ double sm[128];
    int t = threadIdx.x;
    double s = ((g_partial[t] + g_partial[t + 128])
              + (g_partial[t + 256] + g_partial[t + 384]));
    sm[t] = s;
    __syncthreads();
#pragma unroll
    for (int off = 64; off; off >>= 1) {
        if (t < off) sm[t] = sm[t] + sm[t + off];
        __syncthreads();
    }
    if (t == 0) {
        float m = (float)(sm[0] / (double)((long long)N_ * D_));
        out[loss_idx] = 0.25f * m + m;
    }
}

extern "C" void kernel_launch(void* const* d_in, const int* in_sizes, int n_in,
                              void* d_out, int out_size) {
    const float* z  = (const float*)d_in[0];
    const float* cb = (const float*)d_in[1];
    float* out = (float*)d_out;

    const int zq_elems = N_ * C_;               // 1048576
    const int write_zq = (out_size >= zq_elems) ? 1 : 0;

    vq_ee_kernel<<<4, 256>>>(cb);
    vq_main_kernel<<<NBLK, TPB>>>(z, cb, out, write_zq);

    if (out_size == 1) {
        vq_finalize_kernel<<<1, 128>>>(out, 0);
    } else if (out_size > zq_elems) {
        vq_finalize_kernel<<<1, 128>>>(out, zq_elems);
    }
}

// round 3
// speedup vs baseline: 1.3476x; 1.0107x over previous
#include <cuda_runtime.h>

// VectorQuantizer: z (16,64,64,64) fp32, codebook (1024,64) fp32
// out = [z_q flattened (b,c,h,w) : 1048576 floats][loss : 1 float]
//
// fp32 mandatory: one argmin flip vs reference costs ~5e-3 rel_err (> 1e-3).
// Distance loop: packed fma.rn.f32x2 over embedding dim; accumulation order
// (4 residue partials, (r0+r1)+(r2+r3), d = fl(fl(zz+ee) - 2*dot)) is
// bit-identical to the validated round-1/2 kernels -> zero argmin flips.
// This round: register-pressure fix — z kept ONLY in packed f32x2 form in the
// main loop (64 regs); epilogue reloads z from gmem. Frees 64 pinned regs,
// restoring occupancy so the FFMA2 pipe stays fed.

#define B_    16
#define C_    64
#define HW_   4096
#define N_    (B_ * HW_)       // 65536 vectors
#define NE_   1024
#define D_    64
#define TPB   128
#define NBLK  (N_ / TPB)       // 512 blocks
#define CHUNK 128              // codebook entries staged in smem per iter (32KB)

typedef unsigned long long ull;

__device__ double g_partial[NBLK];
__device__ float  g_ee[NE_];

#define FMA_F32X2(d, a, b, c) \
    asm("fma.rn.f32x2 %0, %1, %2, %3;" : "=l"(d) : "l"(a), "l"(b), "l"(c))
#define PACK_F32X2(out, lo, hi) \
    asm("mov.b64 %0, {%1, %2};" : "=l"(out) : "r"(lo), "r"(hi))
#define UNPACK_F32X2(lo, hi, in) \
    asm("mov.b64 {%0, %1}, %2;" : "=r"(lo), "=r"(hi) : "l"(in))

// ||e_k||^2 — sequential fmaf over ascending c (order is load-bearing).
__global__ void vq_ee_kernel(const float* __restrict__ cb) {
    int k = blockIdx.x * blockDim.x + threadIdx.x;
    if (k < NE_) {
        const float4* e = (const float4*)(cb + (size_t)k * D_);
        float s = 0.f;
#pragma unroll
        for (int c = 0; c < D_ / 4; c++) {
            float4 v = e[c];
            s = fmaf(v.x, v.x, s);
            s = fmaf(v.y, v.y, s);
            s = fmaf(v.z, v.z, s);
            s = fmaf(v.w, v.w, s);
        }
        g_ee[k] = s;
    }
}

__global__ __launch_bounds__(TPB) void vq_main_kernel(
    const float* __restrict__ z, const float* __restrict__ cb,
    float* __restrict__ out, int write_zq)
{
    __shared__ __align__(16) float s_e[CHUNK * D_];   // 32 KB
    __shared__ float  s_ee[CHUNK];
    __shared__ double s_red[TPB / 32];

    const int n  = blockIdx.x * TPB + threadIdx.x;
    const int b  = n / HW_;
    const int hw = n - b * HW_;
    const float* zbase = z + (size_t)b * (C_ * HW_) + hw;

    // Load z; compute zz with the validated sequential fmaf order; keep z
    // ONLY as packed f32x2 (dims 2j,2j+1) — no scalar copy held across loop.
    ull   z2[D_ / 2];
    float zz = 0.f;
#pragma unroll
    for (int j = 0; j < D_ / 2; j++) {
        float lo = zbase[(size_t)(2 * j)     * HW_];
        float hi = zbase[(size_t)(2 * j + 1) * HW_];
        zz = fmaf(lo, lo, zz);
        zz = fmaf(hi, hi, zz);
        PACK_F32X2(z2[j], __float_as_uint(lo), __float_as_uint(hi));
    }

    float best_d = 3.402823466e38f;
    int   best_i = 0;

    for (int k0 = 0; k0 < NE_; k0 += CHUNK) {
        __syncthreads();
        {   // cooperative coalesced chunk load
            const float4* src = (const float4*)(cb + (size_t)k0 * D_);
            float4* dst = (float4*)s_e;
#pragma unroll
            for (int i = 0; i < CHUNK * D_ / 4 / TPB; i++)
                dst[threadIdx.x + i * TPB] = src[threadIdx.x + i * TPB];
            s_ee[threadIdx.x] = g_ee[k0 + threadIdx.x];   // CHUNK == TPB
        }
        __syncthreads();

#pragma unroll 4
        for (int k = 0; k < CHUNK; k++) {
            const ulonglong2* e2 = (const ulonglong2*)(s_e + k * D_);
            ull a0 = 0ull, a1 = 0ull;   // bitwise {0.f, 0.f}
#pragma unroll
            for (int j = 0; j < D_ / 4; j++) {
                ulonglong2 ev = e2[j];            // broadcast LDS.128
                FMA_F32X2(a0, z2[2 * j],     ev.x, a0);   // residues 0,1
                FMA_F32X2(a1, z2[2 * j + 1], ev.y, a1);   // residues 2,3
            }
            unsigned r0, r1, r2, r3;
            UNPACK_F32X2(r0, r1, a0);
            UNPACK_F32X2(r2, r3, a1);
            // validated reduction order: (res0+res1)+(res2+res3)
            float dot = __fadd_rn(__fadd_rn(__uint_as_float(r0), __uint_as_float(r1)),
                                  __fadd_rn(__uint_as_float(r2), __uint_as_float(r3)));
            float d = __fadd_rn(__fadd_rn(zz, s_ee[k]), -2.0f * dot);
            if (d < best_d) { best_d = d; best_i = k0 + k; }  // strict <: first occurrence
        }
    }

    // Epilogue: reload z (coalesced), gather winning entry, emit z_q,
    // accumulate loss in fp64.
    const float* eb = cb + (size_t)best_i * D_;
    float* obase = out + (size_t)b * (C_ * HW_) + hw;
    double lsum = 0.0;
#pragma unroll
    for (int c = 0; c < D_; c++) {
        float e  = __ldg(eb + c);
        float zv = zbase[(size_t)c * HW_];
        float diff = e - zv;
        lsum += (double)diff * (double)diff;
        if (write_zq) obase[(size_t)c * HW_] = e;
    }

#pragma unroll
    for (int off = 16; off; off >>= 1)
        lsum += __shfl_down_sync(0xffffffffu, lsum, off);
    const int lane = threadIdx.x & 31;
    const int wid  = threadIdx.x >> 5;
    if (lane == 0) s_red[wid] = lsum;
    __syncthreads();
    if (threadIdx.x == 0) {
        double t = 0.0;
#pragma unroll
        for (int w = 0; w < TPB / 32; w++) t += s_red[w];
        g_partial[blockIdx.x] = t;
    }
}

// Deterministic parallel finalize: fixed-shape tree over 512 partials.
__global__ void vq_finalize_kernel(float* __restrict__ out, int loss_idx) {
    __shared__ double sm[128];
    int t = threadIdx.x;
    double s = ((g_partial[t] + g_partial[t + 128])
              + (g_partial[t + 256] + g_partial[t + 384]));
    sm[t] = s;
    __syncthreads();
#pragma unroll
    for (int off = 64; off; off >>= 1) {
        if (t < off) sm[t] = sm[t] + sm[t + off];
        __syncthreads();
    }
    if (t == 0) {
        float m = (float)(sm[0] / (double)((long long)N_ * D_));
        out[loss_idx] = 0.25f * m + m;
    }
}

extern "C" void kernel_launch(void* const* d_in, const int* in_sizes, int n_in,
                              void* d_out, int out_size) {
    const float* z  = (const float*)d_in[0];
    const float* cb = (const float*)d_in[1];
    float* out = (float*)d_out;

    const int zq_elems = N_ * C_;               // 1048576
    const int write_zq = (out_size >= zq_elems) ? 1 : 0;

    vq_ee_kernel<<<4, 256>>>(cb);
    vq_main_kernel<<<NBLK, TPB>>>(z, cb, out, write_zq);

    if (out_size == 1) {
        vq_finalize_kernel<<<1, 128>>>(out, 0);
    } else if (out_size > zq_elems) {
        vq_finalize_kernel<<<1, 128>>>(out, zq_elems);
    }
}

// round 4
// speedup vs baseline: 1.5703x; 1.1653x over previous
#include <cuda_runtime.h>

// VectorQuantizer: z (16,64,64,64) fp32, codebook (1024,64) fp32
// out = [z_q flattened (b,c,h,w) : 1048576 floats][loss : 1 float]
//
// fp32 mandatory: one argmin flip vs reference costs ~5e-3 rel_err (> 1e-3).
// Round 4: LDS/FMA co-bound fix. Each thread processes V=2 vectors so each
// broadcast LDS.128 of a codebook segment feeds 4 FFMA2 (was 2). LDS pipe
// drops to ~half the FFMA2-pipe floor -> FMA becomes the sole bottleneck.
// All rounding structure (zz/ee sequential fmaf, (r0+r1)+(r2+r3) dot
// reduction, d = fl(fl(zz+ee) - 2*dot), strict <) is bit-identical to the
// validated kernels -> zero argmin flips.
// Single fused kernel: per-block ee precompute (L2-hot), last-block-done
// deterministic loss finalize (fenced counter, fixed-shape fp64 tree).

#define B_    16
#define C_    64
#define HW_   4096
#define N_    (B_ * HW_)       // 65536 vectors
#define NE_   1024
#define D_    64
#define TPB   128
#define VPT   2                // vectors per thread
#define VPB   (TPB * VPT)      // 256 vectors per block
#define NBLK  (N_ / VPB)       // 256 blocks
#define CHUNK 128              // codebook entries staged in smem per iter (32KB)

typedef unsigned long long ull;

__device__ double   g_partial[NBLK];
__device__ unsigned g_done;    // zero-initialized at module load; reset each run

#define FMA_F32X2(d, a, b, c) \
    asm("fma.rn.f32x2 %0, %1, %2, %3;" : "=l"(d) : "l"(a), "l"(b), "l"(c))
#define PACK_F32X2(out, lo, hi) \
    asm("mov.b64 %0, {%1, %2};" : "=l"(out) : "r"(lo), "r"(hi))
#define UNPACK_F32X2(lo, hi, in) \
    asm("mov.b64 {%0, %1}, %2;" : "=r"(lo), "=r"(hi) : "l"(in))

__global__ __launch_bounds__(TPB, 2) void vq_main_kernel(
    const float* __restrict__ z, const float* __restrict__ cb,
    float* __restrict__ out, int write_zq, int loss_idx)
{
    __shared__ __align__(16) float s_e[CHUNK * D_];   // 32 KB
    __shared__ float  s_ee[NE_];                      // 4 KB: all ||e||^2
    __shared__ double s_red[TPB];

    // --- per-block ee precompute (bit-identical fmaf order: ascending c) ---
    for (int e = threadIdx.x; e < NE_; e += TPB) {
        const float4* ep = (const float4*)(cb + (size_t)e * D_);
        float s = 0.f;
#pragma unroll
        for (int c = 0; c < D_ / 4; c++) {
            float4 v = ep[c];
            s = fmaf(v.x, v.x, s);
            s = fmaf(v.y, v.y, s);
            s = fmaf(v.z, v.z, s);
            s = fmaf(v.w, v.w, s);
        }
        s_ee[e] = s;
    }

    // --- load two z vectors, packed f32x2 along the embedding dim ---
    const int n0 = blockIdx.x * VPB + threadIdx.x;   // vector A
    const int n1 = n0 + TPB;                          // vector B
    const int bA = n0 / HW_, hwA = n0 - bA * HW_;
    const int bB = n1 / HW_, hwB = n1 - bB * HW_;
    const float* zA = z + (size_t)bA * (C_ * HW_) + hwA;
    const float* zB = z + (size_t)bB * (C_ * HW_) + hwB;

    ull z2a[D_ / 2], z2b[D_ / 2];
    float zzA = 0.f, zzB = 0.f;
#pragma unroll
    for (int j = 0; j < D_ / 2; j++) {
        float la = zA[(size_t)(2 * j) * HW_], ha = zA[(size_t)(2 * j + 1) * HW_];
        float lb = zB[(size_t)(2 * j) * HW_], hb = zB[(size_t)(2 * j + 1) * HW_];
        zzA = fmaf(la, la, zzA); zzA = fmaf(ha, ha, zzA);
        zzB = fmaf(lb, lb, zzB); zzB = fmaf(hb, hb, zzB);
        PACK_F32X2(z2a[j], __float_as_uint(la), __float_as_uint(ha));
        PACK_F32X2(z2b[j], __float_as_uint(lb), __float_as_uint(hb));
    }

    float bestdA = 3.402823466e38f, bestdB = 3.402823466e38f;
    int   bestiA = 0,               bestiB = 0;

    for (int k0 = 0; k0 < NE_; k0 += CHUNK) {
        __syncthreads();
        {   // cooperative coalesced chunk load: CHUNK*D_/4 = 2048 float4
            const float4* src = (const float4*)(cb + (size_t)k0 * D_);
            float4* dst = (float4*)s_e;
#pragma unroll
            for (int i = 0; i < CHUNK * D_ / 4 / TPB; i++)
                dst[threadIdx.x + i * TPB] = src[threadIdx.x + i * TPB];
        }
        __syncthreads();

#pragma unroll 2
        for (int k = 0; k < CHUNK; k++) {
            const ulonglong2* e2 = (const ulonglong2*)(s_e + k * D_);
            ull a0 = 0ull, a1 = 0ull;   // vector A: residues {0,1}, {2,3}
            ull b0 = 0ull, b1 = 0ull;   // vector B
#pragma unroll
            for (int j = 0; j < D_ / 4; j++) {
                ulonglong2 ev = e2[j];            // one broadcast LDS.128 -> 4 FFMA2
                FMA_F32X2(a0, z2a[2 * j],     ev.x, a0);
                FMA_F32X2(b0, z2b[2 * j],     ev.x, b0);
                FMA_F32X2(a1, z2a[2 * j + 1], ev.y, a1);
                FMA_F32X2(b1, z2b[2 * j + 1], ev.y, b1);
            }
            float ee = s_ee[k0 + k];   // broadcast
            unsigned r0, r1, r2, r3;
            UNPACK_F32X2(r0, r1, a0);
            UNPACK_F32X2(r2, r3, a1);
            float dotA = __fadd_rn(__fadd_rn(__uint_as_float(r0), __uint_as_float(r1)),
                                   __fadd_rn(__uint_as_float(r2), __uint_as_float(r3)));
            float dA = __fadd_rn(__fadd_rn(zzA, ee), -2.0f * dotA);
            if (dA < bestdA) { bestdA = dA; bestiA = k0 + k; }
            UNPACK_F32X2(r0, r1, b0);
            UNPACK_F32X2(r2, r3, b1);
            float dotB = __fadd_rn(__fadd_rn(__uint_as_float(r0), __uint_as_float(r1)),
                                   __fadd_rn(__uint_as_float(r2), __uint_as_float(r3)));
            float dB = __fadd_rn(__fadd_rn(zzB, ee), -2.0f * dotB);
            if (dB < bestdB) { bestdB = dB; bestiB = k0 + k; }
        }
    }

    // --- epilogue: gather winners, emit z_q, fp64 loss accumulation ---
    const float* ea = cb + (size_t)bestiA * D_;
    const float* eb = cb + (size_t)bestiB * D_;
    float* oA = out + (size_t)bA * (C_ * HW_) + hwA;
    float* oB = out + (size_t)bB * (C_ * HW_) + hwB;
    double lsum = 0.0;
#pragma unroll
    for (int c = 0; c < D_; c++) {
        float eva = __ldg(ea + c);
        float evb = __ldg(eb + c);
        float dfa = eva - zA[(size_t)c * HW_];
        float dfb = evb - zB[(size_t)c * HW_];
        lsum += (double)dfa * (double)dfa;
        lsum += (double)dfb * (double)dfb;
        if (write_zq) {
            oA[(size_t)c * HW_] = eva;
            oB[(size_t)c * HW_] = evb;
        }
    }

    // deterministic block reduction
#pragma unroll
    for (int off = 16; off; off >>= 1)
        lsum += __shfl_down_sync(0xffffffffu, lsum, off);
    const int lane = threadIdx.x & 31;
    const int wid  = threadIdx.x >> 5;
    if (lane == 0) s_red[wid] = lsum;
    __syncthreads();
    if (threadIdx.x == 0) {
        double t = 0.0;
#pragma unroll
        for (int w = 0; w < TPB / 32; w++) t += s_red[w];
        g_partial[blockIdx.x] = t;
    }

    if (loss_idx < 0) return;

    // --- last-block-done deterministic finalize ---
    __shared__ unsigned s_is_last;
    if (threadIdx.x == 0) {
        __threadfence();
        s_is_last = (atomicAdd(&g_done, 1u) == NBLK - 1) ? 1u : 0u;
    }
    __syncthreads();
    if (s_is_last) {
        __threadfence();   // make all blocks' g_partial writes visible
        const int t = threadIdx.x;
        double s = g_partial[t] + g_partial[t + TPB];   // 256 partials, fixed shape
        s_red[t] = s;
        __syncthreads();
#pragma unroll
        for (int off = TPB / 2; off; off >>= 1) {
            if (t < off) s_red[t] = s_red[t] + s_red[t + off];
            __syncthreads();
        }
        if (t == 0) {
            float m = (float)(s_red[0] / (double)((long long)N_ * D_));
            out[loss_idx] = 0.25f * m + m;
            g_done = 0;    // reset for next graph replay
        }
    }
}

extern "C" void kernel_launch(void* const* d_in, const int* in_sizes, int n_in,
                              void* d_out, int out_size) {
    const float* z  = (const float*)d_in[0];
    const float* cb = (const float*)d_in[1];
    float* out = (float*)d_out;

    const int zq_elems = N_ * C_;               // 1048576
    const int write_zq = (out_size >= zq_elems) ? 1 : 0;
    int loss_idx = -1;
    if (out_size == 1)            loss_idx = 0;            // loss-only output
    else if (out_size > zq_elems) loss_idx = zq_elems;     // [z_q | loss]

    vq_main_kernel<<<NBLK, TPB>>>(z, cb, out, write_zq, loss_idx);
}